// round 5
// baseline (speedup 1.0000x reference)
#include <cuda_runtime.h>
#include <math.h>
#include <stdint.h>

#define B_     64
#define T_     1024
#define VOCAB_ 256
#define EMB_   128
#define HID_   512

#define QG  4      // batch groups (16 batches each)
#define PG  32     // column groups (16 cols each)
#define BQ  16
#define CJ  16
#define NCTA (QG*PG)
#define RNN_THREADS 128

#define HDUP 34    // hT_a row stride (duplicated {h,h} pairs: 32 data words + 2 pad)
#define HS1  18    // hT_b row stride (16 data words + 2 pad)
#define RSTR 18    // reduction buffer row stride per batch

typedef unsigned long long u64;

__device__ __forceinline__ void fma2(u64& acc, u64 a, u64 b) {
    asm("fma.rn.f32x2 %0, %1, %2, %0;" : "+l"(acc) : "l"(a), "l"(b));
}
__device__ __forceinline__ void fadd2(u64& a, u64 b) {
    asm("add.rn.f32x2 %0, %0, %1;" : "+l"(a) : "l"(b));
}
__device__ __forceinline__ u64 pack2(float x) {
    u64 r; unsigned u = __float_as_uint(x);
    asm("mov.b64 %0, {%1, %1};" : "=l"(r) : "r"(u));
    return r;
}
__device__ __forceinline__ float2 unpack2(u64 v) {
    unsigned lo, hi;
    asm("mov.b64 {%0, %1}, %2;" : "=r"(lo), "=r"(hi) : "l"(v));
    return make_float2(__uint_as_float(lo), __uint_as_float(hi));
}

// ---------------- device global scratch ----------------
__device__ __align__(16) float g_E2[VOCAB_ * HID_];
__device__ __align__(16) float g_h0[2][B_ * HID_];
__device__ __align__(16) float g_h1[2][B_ * HID_];
__device__ __align__(16) float g_hout[(size_t)B_ * T_ * HID_];
__device__ __align__(128) unsigned g_flags[QG][PG];

// ---------------- prep ----------------
__global__ void prep_kernel(const float* __restrict__ emb,
                            const float* __restrict__ w_ih0,
                            const float* __restrict__ b_ih0,
                            const float* __restrict__ b_hh0)
{
    int v = blockIdx.x;
    __shared__ float se[EMB_];
    for (int k = threadIdx.x; k < EMB_; k += blockDim.x) se[k] = emb[v * EMB_ + k];
    __syncthreads();
    for (int j = threadIdx.x; j < HID_; j += blockDim.x) {
        const float* wr = w_ih0 + (size_t)j * EMB_;
        float s = b_ih0[j] + b_hh0[j];
        #pragma unroll 8
        for (int k = 0; k < EMB_; k++) s = fmaf(se[k], wr[k], s);
        g_E2[v * HID_ + j] = s;
    }
    int gt = blockIdx.x * blockDim.x + threadIdx.x;
    // zero h1 parity-0 buffer (exactly 32768 threads)
    g_h1[0][gt] = 0.0f;
    if (gt < QG * PG) ((unsigned*)g_flags)[gt] = 0u;
}

// ---------------- persistent RNN kernel ----------------
__global__ void __launch_bounds__(RNN_THREADS, 1)
rnn_kernel(const int* __restrict__ xg,
           const float* __restrict__ w_hh0,
           const float* __restrict__ w_ih1,
           const float* __restrict__ b_ih1,
           const float* __restrict__ w_hh1,
           const float* __restrict__ b_hh1)
{
    extern __shared__ float smem[];
    float* wT0  = smem;                    // [512][16]  w_hh0^T
    float* wT1i = wT0  + HID_ * CJ;        // [512][16]  w_ih1^T
    float* wT1h = wT1i + HID_ * CJ;        // [512][16]  w_hh1^T
    float* hT_a = wT1h + HID_ * CJ;        // [512][HDUP] h0 transposed, duplicated pairs
    float* hT_b = hT_a + HID_ * HDUP;      // [512][HS1]  h1_prev transposed
    float* red  = hT_b + HID_ * HS1;       // [4][16][RSTR] cross-warp partials

    const int tid  = threadIdx.x;
    const int q    = blockIdx.x >> 5;      // batch group
    const int p    = blockIdx.x & 31;      // column group
    const int j0   = p * CJ;
    const int b0   = q * BQ;
    const int lane = tid & 31;
    const int kq   = tid >> 5;             // warp = k-quarter
    const int jq   = lane & 3;             // j quad (4 cols)
    const int bq   = lane >> 2;            // batch pair (2 batches)

    // epilogue/staging thread mapping
    const int rb = tid >> 3;               // batch 0..15
    const int rj = (tid & 7) * 2;          // even col 0..14
    const int c4 = tid & 7;                // staging float4 col

    // ---- one-time: transposed weight slices (coalesced LDG, scattered STS) ----
    for (int idx = tid; idx < HID_ * CJ; idx += RNN_THREADS) {
        int k = idx & 511, j = idx >> 9;
        wT0 [k * CJ + j] = w_hh0[(size_t)(j0 + j) * HID_ + k];
        wT1i[k * CJ + j] = w_ih1[(size_t)(j0 + j) * HID_ + k];
        wT1h[k * CJ + j] = w_hh1[(size_t)(j0 + j) * HID_ + k];
    }
    // zero hT_a (h0_{-1} = 0)
    for (int idx = tid; idx < HID_ * HDUP / 4; idx += RNN_THREADS)
        *(float4*)(hT_a + idx * 4) = make_float4(0.f, 0.f, 0.f, 0.f);

    // per-thread layer1 bias pair
    float2 biasv;
    biasv.x = b_ih1[j0 + rj]     + b_hh1[j0 + rj];
    biasv.y = b_ih1[j0 + rj + 1] + b_hh1[j0 + rj + 1];
    __syncthreads();

    const float* wp0 = wT0  + (kq * 128) * CJ + jq * 4;
    const float* wpi = wT1i + (kq * 128) * CJ + jq * 4;
    const float* wph = wT1h + (kq * 128) * CJ + jq * 4;
    const float* hpa = hT_a + (kq * 128) * HDUP + bq * 4;
    const float* hpb = hT_b + (kq * 128) * HS1  + bq * 2;
    float* rp = red + kq * 16 * RSTR + (bq * 2) * RSTR + jq * 4;

    for (int t = 0; t < T_; t++) {
        const int wbuf   = (t & 1) ^ 1;
        const int h1prev = t & 1;

        __syncthreads();   // protect red from previous step's readers

        // prefetch token + E2 pair for this thread's epilogue output
        int tok = __ldg(xg + (size_t)(b0 + rb) * T_ + t);
        float2 e2v = __ldg((const float2*)(g_E2 + (size_t)tok * HID_ + j0 + rj));

        // ---- layer 0: partial over this warp's k-quarter ----
        {
            u64 a00 = 0, a10 = 0, a01 = 0, a11 = 0;
            #pragma unroll 8
            for (int k = 0; k < 128; k++) {
                ulonglong2 wv = *(const ulonglong2*)(wp0 + k * CJ);
                u64 hb0 = *(const u64*)(hpa + k * HDUP);
                u64 hb1 = *(const u64*)(hpa + k * HDUP + 2);
                fma2(a00, wv.x, hb0); fma2(a10, wv.y, hb0);
                fma2(a01, wv.x, hb1); fma2(a11, wv.y, hb1);
            }
            *(u64*)(rp)            = a00;
            *(u64*)(rp + 2)        = a10;
            *(u64*)(rp + RSTR)     = a01;
            *(u64*)(rp + RSTR + 2) = a11;
        }
        __syncthreads();

        // ---- reduce + tanh + publish h0 ----
        {
            const float* rr = red + rb * RSTR + rj;
            u64 s = *(const u64*)(rr);
            fadd2(s, *(const u64*)(rr + 16 * RSTR));
            fadd2(s, *(const u64*)(rr + 32 * RSTR));
            fadd2(s, *(const u64*)(rr + 48 * RSTR));
            float2 sf = unpack2(s);
            float v0 = tanhf(sf.x + e2v.x);
            float v1 = tanhf(sf.y + e2v.y);
            float2 hv = make_float2(v0, v1);
            __stcg((float2*)(g_h0[wbuf] + (size_t)(b0 + rb) * HID_ + j0 + rj), hv);
        }

        // ---- group barrier: flag store + parallel poll ----
        __syncthreads();
        if (tid == 0) {
            asm volatile("fence.acq_rel.gpu;");
            asm volatile("st.release.gpu.global.u32 [%0], %1;"
                         :: "l"(&g_flags[q][p]), "r"((unsigned)(t + 1)) : "memory");
        }
        if (tid < PG) {
            unsigned v;
            do {
                asm volatile("ld.acquire.gpu.global.u32 %0, [%1];"
                             : "=r"(v) : "l"(&g_flags[q][tid]) : "memory");
            } while (!__all_sync(0xffffffffu, v >= (unsigned)(t + 1)));
        }
        __syncthreads();

        // ---- stage h0_t -> hT_a (transposed, duplicated), h1_{t-1} -> hT_b ----
        {
            const float* g0 = g_h0[wbuf]   + (size_t)b0 * HID_;
            const float* g1 = g_h1[h1prev] + (size_t)b0 * HID_;
            #pragma unroll 4
            for (int cc = 0; cc < 16; cc++) {
                int c = cc * 32 + c4 * 4;
                float4 v = __ldcg((const float4*)(g0 + (size_t)rb * HID_ + c));
                *(u64*)(hT_a + (c + 0) * HDUP + 2 * rb) = pack2(v.x);
                *(u64*)(hT_a + (c + 1) * HDUP + 2 * rb) = pack2(v.y);
                *(u64*)(hT_a + (c + 2) * HDUP + 2 * rb) = pack2(v.z);
                *(u64*)(hT_a + (c + 3) * HDUP + 2 * rb) = pack2(v.w);
            }
            #pragma unroll 4
            for (int cc = 0; cc < 16; cc++) {
                int c = cc * 32 + c4 * 4;
                float4 v = __ldcg((const float4*)(g1 + (size_t)rb * HID_ + c));
                hT_b[(c + 0) * HS1 + rb] = v.x;
                hT_b[(c + 1) * HS1 + rb] = v.y;
                hT_b[(c + 2) * HS1 + rb] = v.z;
                hT_b[(c + 3) * HS1 + rb] = v.w;
            }
        }
        __syncthreads();

        // ---- layer 1: partial over this warp's k-quarter (both inputs) ----
        {
            u64 a00 = 0, a10 = 0, a01 = 0, a11 = 0;
            #pragma unroll 4
            for (int k = 0; k < 128; k++) {
                ulonglong2 wvi = *(const ulonglong2*)(wpi + k * CJ);
                ulonglong2 wvh = *(const ulonglong2*)(wph + k * CJ);
                u64 hb0 = *(const u64*)(hpa + k * HDUP);
                u64 hb1 = *(const u64*)(hpa + k * HDUP + 2);
                u64 q2  = *(const u64*)(hpb + k * HS1);
                float2 qf = unpack2(q2);
                u64 qb0 = pack2(qf.x);
                u64 qb1 = pack2(qf.y);
                fma2(a00, wvi.x, hb0); fma2(a10, wvi.y, hb0);
                fma2(a01, wvi.x, hb1); fma2(a11, wvi.y, hb1);
                fma2(a00, wvh.x, qb0); fma2(a10, wvh.y, qb0);
                fma2(a01, wvh.x, qb1); fma2(a11, wvh.y, qb1);
            }
            *(u64*)(rp)            = a00;
            *(u64*)(rp + 2)        = a10;
            *(u64*)(rp + RSTR)     = a01;
            *(u64*)(rp + RSTR + 2) = a11;
        }
        __syncthreads();

        // ---- reduce + tanh + publish h1 + record output ----
        {
            const float* rr = red + rb * RSTR + rj;
            u64 s = *(const u64*)(rr);
            fadd2(s, *(const u64*)(rr + 16 * RSTR));
            fadd2(s, *(const u64*)(rr + 32 * RSTR));
            fadd2(s, *(const u64*)(rr + 48 * RSTR));
            float2 sf = unpack2(s);
            float v0 = tanhf(sf.x + biasv.x);
            float v1 = tanhf(sf.y + biasv.y);
            float2 hv = make_float2(v0, v1);
            __stcg((float2*)(g_h1[wbuf] + (size_t)(b0 + rb) * HID_ + j0 + rj), hv);
            __stcg((float2*)(g_hout + ((size_t)(b0 + rb) * T_ + t) * HID_ + j0 + rj), hv);
        }
    }
}

// ---------------- final FC: logits = g_hout @ fc_w^T + fc_b ----------------
#define FC_BM 64
#define FC_BN 64
#define FC_BK 32

__global__ void __launch_bounds__(256)
fc_kernel(const float* __restrict__ fc_w,
          const float* __restrict__ fc_b,
          float* __restrict__ out)
{
    __shared__ float As[FC_BK][FC_BM];
    __shared__ float Bs[FC_BK][FC_BN];

    const int tx = threadIdx.x & 15;
    const int ty = threadIdx.x >> 4;
    const size_t i0 = (size_t)blockIdx.x * FC_BM;
    const int v0 = blockIdx.y * FC_BN;

    const int lr = threadIdx.x >> 2;
    const int lc = threadIdx.x & 3;

    const float* Abase = g_hout + i0 * HID_;
    const float* Bbase = fc_w + (size_t)v0 * HID_;

    float acc[4][4] = {};

    for (int k0 = 0; k0 < HID_; k0 += FC_BK) {
        float4 a0 = *(const float4*)(Abase + (size_t)lr * HID_ + k0 + lc * 4);
        float4 a1 = *(const float4*)(Abase + (size_t)lr * HID_ + k0 + 16 + lc * 4);
        float4 w0 = *(const float4*)(Bbase + (size_t)lr * HID_ + k0 + lc * 4);
        float4 w1 = *(const float4*)(Bbase + (size_t)lr * HID_ + k0 + 16 + lc * 4);
        __syncthreads();
        As[lc * 4 + 0][lr] = a0.x; As[lc * 4 + 1][lr] = a0.y;
        As[lc * 4 + 2][lr] = a0.z; As[lc * 4 + 3][lr] = a0.w;
        As[16 + lc * 4 + 0][lr] = a1.x; As[16 + lc * 4 + 1][lr] = a1.y;
        As[16 + lc * 4 + 2][lr] = a1.z; As[16 + lc * 4 + 3][lr] = a1.w;
        Bs[lc * 4 + 0][lr] = w0.x; Bs[lc * 4 + 1][lr] = w0.y;
        Bs[lc * 4 + 2][lr] = w0.z; Bs[lc * 4 + 3][lr] = w0.w;
        Bs[16 + lc * 4 + 0][lr] = w1.x; Bs[16 + lc * 4 + 1][lr] = w1.y;
        Bs[16 + lc * 4 + 2][lr] = w1.z; Bs[16 + lc * 4 + 3][lr] = w1.w;
        __syncthreads();
        #pragma unroll
        for (int k = 0; k < FC_BK; k++) {
            float4 av = *(const float4*)&As[k][ty * 4];
            float4 bv = *(const float4*)&Bs[k][tx * 4];
            acc[0][0] = fmaf(av.x, bv.x, acc[0][0]); acc[0][1] = fmaf(av.x, bv.y, acc[0][1]);
            acc[0][2] = fmaf(av.x, bv.z, acc[0][2]); acc[0][3] = fmaf(av.x, bv.w, acc[0][3]);
            acc[1][0] = fmaf(av.y, bv.x, acc[1][0]); acc[1][1] = fmaf(av.y, bv.y, acc[1][1]);
            acc[1][2] = fmaf(av.y, bv.z, acc[1][2]); acc[1][3] = fmaf(av.y, bv.w, acc[1][3]);
            acc[2][0] = fmaf(av.z, bv.x, acc[2][0]); acc[2][1] = fmaf(av.z, bv.y, acc[2][1]);
            acc[2][2] = fmaf(av.z, bv.z, acc[2][2]); acc[2][3] = fmaf(av.z, bv.w, acc[2][3]);
            acc[3][0] = fmaf(av.w, bv.x, acc[3][0]); acc[3][1] = fmaf(av.w, bv.y, acc[3][1]);
            acc[3][2] = fmaf(av.w, bv.z, acc[3][2]); acc[3][3] = fmaf(av.w, bv.w, acc[3][3]);
        }
    }

    float4 bb = *(const float4*)(fc_b + v0 + tx * 4);
    #pragma unroll
    for (int m = 0; m < 4; m++) {
        float4 r;
        r.x = acc[m][0] + bb.x;
        r.y = acc[m][1] + bb.y;
        r.z = acc[m][2] + bb.z;
        r.w = acc[m][3] + bb.w;
        *(float4*)(out + (i0 + ty * 4 + m) * VOCAB_ + v0 + tx * 4) = r;
    }
}

// ---------------- launch ----------------
extern "C" void kernel_launch(void* const* d_in, const int* in_sizes, int n_in,
                              void* d_out, int out_size)
{
    const int* x        = (const int*)d_in[0];
    const float* emb    = (const float*)d_in[1];
    const float* w_ih0  = (const float*)d_in[2];
    const float* b_ih0  = (const float*)d_in[3];
    const float* w_hh0  = (const float*)d_in[4];
    const float* b_hh0  = (const float*)d_in[5];
    const float* w_ih1  = (const float*)d_in[6];
    const float* b_ih1  = (const float*)d_in[7];
    const float* w_hh1  = (const float*)d_in[8];
    const float* b_hh1  = (const float*)d_in[9];
    const float* fc_w   = (const float*)d_in[10];
    const float* fc_b   = (const float*)d_in[11];
    float* out = (float*)d_out;

    const size_t smem_bytes =
        (size_t)(3 * HID_ * CJ + HID_ * HDUP + HID_ * HS1 + 4 * 16 * RSTR) * sizeof(float);
    cudaFuncSetAttribute(rnn_kernel, cudaFuncAttributeMaxDynamicSharedMemorySize,
                         (int)smem_bytes);

    prep_kernel<<<VOCAB_, 128>>>(emb, w_ih0, b_ih0, b_hh0);
    rnn_kernel<<<NCTA, RNN_THREADS, smem_bytes>>>(x, w_hh0, w_ih1, b_ih1, w_hh1, b_hh1);
    fc_kernel<<<dim3((B_ * T_) / FC_BM, VOCAB_ / FC_BN), 256>>>(fc_w, fc_b, out);
}